// round 4
// baseline (speedup 1.0000x reference)
#include <cuda_runtime.h>
#include <cstdint>
#include <math.h>

#define M_DIM 16384
#define K_DIM 768
#define N_DIM 3072

// ---------------- scratch (no cudaMalloc allowed) ----------------
__device__ int8_t g_Ah[M_DIM * K_DIM];
__device__ int8_t g_Al[M_DIM * K_DIM];
__device__ int8_t g_Bh[N_DIM * K_DIM];   // W transposed [N, K]
__device__ int8_t g_Bl[N_DIM * K_DIM];
__device__ float  g_sa[M_DIM];
__device__ float  g_sb[N_DIM];

// ---------------- helpers ----------------
__device__ __forceinline__ uint32_t smem_u32(const void* p) {
    uint32_t a;
    asm("{ .reg .u64 t; cvta.to.shared.u64 t, %1; cvt.u32.u64 %0, t; }" : "=r"(a) : "l"(p));
    return a;
}
__device__ __forceinline__ void cp_async16(uint32_t dst, const void* src) {
    asm volatile("cp.async.cg.shared.global [%0], [%1], 16;"
                 :: "r"(dst), "l"(__cvta_generic_to_global(src)) : "memory");
}
#define CP_COMMIT() asm volatile("cp.async.commit_group;" ::: "memory")
#define CP_WAIT(n)  asm volatile("cp.async.wait_group %0;" :: "n"(n) : "memory")

__device__ __forceinline__ void ldmatrix_x4(uint32_t* r, uint32_t addr) {
    asm volatile("ldmatrix.sync.aligned.m8n8.x4.shared.b16 {%0,%1,%2,%3}, [%4];"
                 : "=r"(r[0]), "=r"(r[1]), "=r"(r[2]), "=r"(r[3]) : "r"(addr));
}
__device__ __forceinline__ void mma_s8(int* d, const uint32_t* a,
                                       uint32_t b0, uint32_t b1) {
    asm volatile(
        "mma.sync.aligned.m16n8k32.row.col.s32.s8.s8.s32 "
        "{%0,%1,%2,%3}, {%4,%5,%6,%7}, {%8,%9}, {%0,%1,%2,%3};"
        : "+r"(d[0]), "+r"(d[1]), "+r"(d[2]), "+r"(d[3])
        : "r"(a[0]), "r"(a[1]), "r"(a[2]), "r"(a[3]), "r"(b0), "r"(b1));
}

// ---------------------------------------------------------------------------
// Kernel 1: LayerNorm + int8 2-limb quantization (per-row scale)
// ---------------------------------------------------------------------------
__global__ __launch_bounds__(256) void ln_quant_kernel(
    const float* __restrict__ x,
    const float* __restrict__ gamma,
    const float* __restrict__ beta)
{
    const int row = blockIdx.x;
    const int tid = threadIdx.x;
    const float* xr = x + (size_t)row * K_DIM;

    float v0 = xr[tid];
    float v1 = xr[tid + 256];
    float v2 = xr[tid + 512];

    float s  = v0 + v1 + v2;
    float s2 = v0 * v0 + v1 * v1 + v2 * v2;

    __shared__ float red[2][32];
    #pragma unroll
    for (int off = 16; off > 0; off >>= 1) {
        s  += __shfl_xor_sync(0xffffffffu, s,  off);
        s2 += __shfl_xor_sync(0xffffffffu, s2, off);
    }
    const int wid = tid >> 5, lid = tid & 31;
    if (lid == 0) { red[0][wid] = s; red[1][wid] = s2; }
    __syncthreads();
    if (wid == 0) {
        s  = (lid < 8) ? red[0][lid] : 0.0f;
        s2 = (lid < 8) ? red[1][lid] : 0.0f;
        #pragma unroll
        for (int off = 4; off > 0; off >>= 1) {
            s  += __shfl_xor_sync(0xffffffffu, s,  off);
            s2 += __shfl_xor_sync(0xffffffffu, s2, off);
        }
        if (lid == 0) { red[0][0] = s; red[1][0] = s2; }
    }
    __syncthreads();
    const float inv_n = 1.0f / (float)K_DIM;
    const float mu  = red[0][0] * inv_n;
    const float var = fmaxf(red[1][0] * inv_n - mu * mu, 0.0f);
    const float rstd = rsqrtf(var + 1e-12f);
    __syncthreads();

    float xn[3];
    #pragma unroll
    for (int i = 0; i < 3; i++) {
        const int c = tid + i * 256;
        float v = (i == 0) ? v0 : (i == 1 ? v1 : v2);
        xn[i] = (v - mu) * rstd * gamma[c] + beta[c];
    }

    // row max of |xn|
    float mx = fmaxf(fmaxf(fabsf(xn[0]), fabsf(xn[1])), fabsf(xn[2]));
    #pragma unroll
    for (int off = 16; off > 0; off >>= 1)
        mx = fmaxf(mx, __shfl_xor_sync(0xffffffffu, mx, off));
    if (lid == 0) red[0][wid] = mx;
    __syncthreads();
    if (wid == 0) {
        mx = (lid < 8) ? red[0][lid] : 0.0f;
        #pragma unroll
        for (int off = 4; off > 0; off >>= 1)
            mx = fmaxf(mx, __shfl_xor_sync(0xffffffffu, mx, off));
        if (lid == 0) red[0][0] = mx;
    }
    __syncthreads();
    const float mxv = fmaxf(red[0][0], 1e-20f);
    const float inv = 16256.0f / mxv;
    if (tid == 0) g_sa[row] = mxv * (1.0f / 16256.0f);

    #pragma unroll
    for (int i = 0; i < 3; i++) {
        const int c = tid + i * 256;
        float qf = xn[i] * inv;
        float hf = rintf(qf * 0.0078125f);
        float lf = rintf(qf - hf * 128.0f);
        const size_t idx = (size_t)row * K_DIM + c;
        g_Ah[idx] = (int8_t)(int)hf;
        g_Al[idx] = (int8_t)(int)lf;
    }
}

// ---------------------------------------------------------------------------
// Kernel 2: per-output-column (W column = Wt row) max -> g_sb
// ---------------------------------------------------------------------------
__global__ __launch_bounds__(256) void wcolmax_kernel(const float* __restrict__ W)
{
    const int n = blockIdx.x * 256 + threadIdx.x;
    float m = 0.0f;
    #pragma unroll 8
    for (int k = 0; k < K_DIM; k++)
        m = fmaxf(m, fabsf(W[(size_t)k * N_DIM + n]));
    g_sb[n] = fmaxf(m, 1e-20f) * (1.0f / 16256.0f);
}

// ---------------------------------------------------------------------------
// Kernel 3: transpose W [K,N] -> [N,K] with int8 2-limb quantization
// ---------------------------------------------------------------------------
__global__ __launch_bounds__(256) void wquant_kernel(const float* __restrict__ W)
{
    __shared__ float tile[32][33];
    const int tx = threadIdx.x, ty = threadIdx.y;   // block (32, 8)
    const int n0 = blockIdx.x * 32, k0 = blockIdx.y * 32;

    #pragma unroll
    for (int j = 0; j < 4; j++)
        tile[ty + 8 * j][tx] = W[(size_t)(k0 + ty + 8 * j) * N_DIM + n0 + tx];
    __syncthreads();
    #pragma unroll
    for (int j = 0; j < 4; j++) {
        const int n = n0 + ty + 8 * j;
        const float inv = __frcp_rn(g_sb[n]);       // = 16256/max
        float qf = tile[tx][ty + 8 * j] * inv;
        float hf = rintf(qf * 0.0078125f);
        float lf = rintf(qf - hf * 128.0f);
        const size_t idx = (size_t)n * K_DIM + k0 + tx;
        g_Bh[idx] = (int8_t)(int)hf;
        g_Bl[idx] = (int8_t)(int)lf;
    }
}

// ---------------------------------------------------------------------------
// Kernel 4: int8 IMMA GEMM (m16n8k32), 3 passes (hh; hl+lh shared acc)
// CTA 128x128, BK=64, 2-stage cp.async, 8 warps (warp tile 32x64).
// ---------------------------------------------------------------------------
#define BKQ 64
#define ROWB 80                      // 64 data + 16 pad per smem row
#define STAGE (128 * ROWB)           // 10240 B per operand stage
#define NSTEPS 36                    // 3 segments * 12

__global__ __launch_bounds__(256, 1) void gemm_s8_kernel(
    const float* __restrict__ bias, float* __restrict__ C)
{
    __shared__ int8_t As[2][STAGE];
    __shared__ int8_t Bs[2][STAGE];

    const int tid = threadIdx.x;
    const int wid = tid >> 5, lane = tid & 31;
    const int bn = blockIdx.x * 128;
    const int bm = blockIdx.y * 128;
    const int wm = (wid >> 1) * 32;   // 4 warps along M
    const int wn = (wid & 1) * 64;    // 2 warps along N

    int acc_hh[2][8][4];
    int acc_mid[2][8][4];
    #pragma unroll
    for (int mt = 0; mt < 2; mt++)
        #pragma unroll
        for (int nt = 0; nt < 8; nt++)
            #pragma unroll
            for (int q = 0; q < 4; q++) { acc_hh[mt][nt][q] = 0; acc_mid[mt][nt][q] = 0; }

    const uint32_t sA0 = smem_u32(&As[0][0]);
    const uint32_t sB0 = smem_u32(&Bs[0][0]);

    auto load_stage = [&](int st, int stp) {
        const int seg = (stp >= 24) ? 2 : (stp >= 12 ? 1 : 0);
        const int k0 = (stp - seg * 12) * BKQ;
        const int8_t* Asrc = (seg < 2) ? g_Ah : g_Al;
        const int8_t* Bsrc = (seg == 1) ? g_Bl : g_Bh;
        #pragma unroll
        for (int i = 0; i < 2; i++) {
            const int idx = tid + i * 256;       // 0..511
            const int r = idx >> 2, c = idx & 3; // row, 16B chunk
            const uint32_t soff = (uint32_t)(r * ROWB + c * 16);
            cp_async16(sA0 + st * STAGE + soff,
                       Asrc + (size_t)(bm + r) * K_DIM + k0 + c * 16);
            cp_async16(sB0 + st * STAGE + soff,
                       Bsrc + (size_t)(bn + r) * K_DIM + k0 + c * 16);
        }
        CP_COMMIT();
    };

    int step = 0;
    load_stage(0, 0);

#define DO_STEP(ACC)                                                          \
    {                                                                         \
        const int st = step & 1;                                              \
        if (step + 1 < NSTEPS) { load_stage(st ^ 1, step + 1); CP_WAIT(1); }  \
        else { CP_WAIT(0); }                                                  \
        __syncthreads();                                                      \
        _Pragma("unroll")                                                     \
        for (int kk = 0; kk < 2; kk++) {                                      \
            const int chunk = kk * 2 + (lane >> 4);                           \
            uint32_t a[2][4];                                                 \
            _Pragma("unroll")                                                 \
            for (int mt = 0; mt < 2; mt++)                                    \
                ldmatrix_x4(a[mt], sA0 + st * STAGE                           \
                    + (uint32_t)((wm + mt * 16 + (lane & 15)) * ROWB)         \
                    + chunk * 16);                                            \
            uint32_t b[4][4];                                                 \
            _Pragma("unroll")                                                 \
            for (int g = 0; g < 4; g++)                                       \
                ldmatrix_x4(b[g], sB0 + st * STAGE                            \
                    + (uint32_t)((wn + g * 16 + (lane & 15)) * ROWB)          \
                    + chunk * 16);                                            \
            _Pragma("unroll")                                                 \
            for (int mt = 0; mt < 2; mt++)                                    \
                _Pragma("unroll")                                             \
                for (int nt = 0; nt < 8; nt++)                                \
                    mma_s8(ACC[mt][nt], a[mt],                                \
                           b[nt >> 1][nt & 1], b[nt >> 1][2 + (nt & 1)]);     \
        }                                                                     \
        __syncthreads();                                                      \
        step++;                                                               \
    }

    for (int s = 0; s < 12; s++) DO_STEP(acc_hh);    // segment 0: H*H
    for (int s = 0; s < 24; s++) DO_STEP(acc_mid);   // segments 1,2: H*L + L*H
#undef DO_STEP

    // epilogue: recombine + scales + bias + exact erf GELU
    const int r0 = bm + wm + (lane >> 2);
    const int c0 = bn + wn + (lane & 3) * 2;
    float sar[2][2];
    #pragma unroll
    for (int mt = 0; mt < 2; mt++)
        #pragma unroll
        for (int half = 0; half < 2; half++)
            sar[mt][half] = g_sa[r0 + mt * 16 + half * 8];

    #pragma unroll
    for (int nt = 0; nt < 8; nt++) {
        const int col = c0 + nt * 8;
        const float sb0 = g_sb[col],  sb1 = g_sb[col + 1];
        const float bb0 = bias[col],  bb1 = bias[col + 1];
        #pragma unroll
        for (int mt = 0; mt < 2; mt++) {
            #pragma unroll
            for (int half = 0; half < 2; half++) {
                const int row = r0 + mt * 16 + half * 8;
                const float sa = sar[mt][half];
                float f0 = fmaf((float)acc_hh[mt][nt][half * 2 + 0], 16384.0f,
                                (float)acc_mid[mt][nt][half * 2 + 0] * 128.0f);
                float f1 = fmaf((float)acc_hh[mt][nt][half * 2 + 1], 16384.0f,
                                (float)acc_mid[mt][nt][half * 2 + 1] * 128.0f);
                float h0 = f0 * (sa * sb0) + bb0;
                float h1 = f1 * (sa * sb1) + bb1;
                float2 o;
                o.x = 0.5f * h0 * (1.0f + erff(h0 * 0.70710678118654752f));
                o.y = 0.5f * h1 * (1.0f + erff(h1 * 0.70710678118654752f));
                *(float2*)&C[(size_t)row * N_DIM + col] = o;
            }
        }
    }
}

// ---------------------------------------------------------------------------
extern "C" void kernel_launch(void* const* d_in, const int* in_sizes, int n_in,
                              void* d_out, int out_size)
{
    const float* x     = (const float*)d_in[0];
    const float* gamma = (const float*)d_in[1];
    const float* beta  = (const float*)d_in[2];
    const float* W     = (const float*)d_in[3];
    const float* b     = (const float*)d_in[4];
    float* out = (float*)d_out;

    ln_quant_kernel<<<M_DIM, 256>>>(x, gamma, beta);
    wcolmax_kernel<<<N_DIM / 256, 256>>>(W);
    wquant_kernel<<<dim3(N_DIM / 32, K_DIM / 32), dim3(32, 8)>>>(W);
    gemm_s8_kernel<<<dim3(N_DIM / 128, M_DIM / 128), 256>>>(b, out);
}

// round 5
// speedup vs baseline: 5.4465x; 5.4465x over previous
#include <cuda_runtime.h>
#include <cstdint>
#include <math.h>

#define M_DIM 16384
#define K_DIM 768
#define N_DIM 3072

// ---------------- scratch (no cudaMalloc allowed) ----------------
__device__ uint16_t g_A[M_DIM * K_DIM];    // fp16 bits, LN output
__device__ uint16_t g_B[N_DIM * K_DIM];    // fp16 bits, W transposed [N, K]

// ---------------- helpers ----------------
__device__ __forceinline__ uint32_t smem_u32(const void* p) {
    uint32_t a;
    asm("{ .reg .u64 t; cvta.to.shared.u64 t, %1; cvt.u32.u64 %0, t; }" : "=r"(a) : "l"(p));
    return a;
}
__device__ __forceinline__ uint16_t f2h(float x) {
    uint16_t h;
    asm("cvt.rn.f16.f32 %0, %1;" : "=h"(h) : "f"(x));
    return h;
}
__device__ __forceinline__ void cp_async16(uint32_t dst, const void* src) {
    asm volatile("cp.async.cg.shared.global [%0], [%1], 16;"
                 :: "r"(dst), "l"(__cvta_generic_to_global(src)) : "memory");
}
#define CP_COMMIT() asm volatile("cp.async.commit_group;" ::: "memory")
#define CP_WAIT(n)  asm volatile("cp.async.wait_group %0;" :: "n"(n) : "memory")

__device__ __forceinline__ void ldmatrix_x4(uint32_t* r, uint32_t addr) {
    asm volatile("ldmatrix.sync.aligned.m8n8.x4.shared.b16 {%0,%1,%2,%3}, [%4];"
                 : "=r"(r[0]), "=r"(r[1]), "=r"(r[2]), "=r"(r[3]) : "r"(addr));
}
__device__ __forceinline__ void mma_f16(float* d, const uint32_t* a,
                                        uint32_t b0, uint32_t b1) {
    asm volatile(
        "mma.sync.aligned.m16n8k16.row.col.f32.f16.f16.f32 "
        "{%0,%1,%2,%3}, {%4,%5,%6,%7}, {%8,%9}, {%0,%1,%2,%3};"
        : "+f"(d[0]), "+f"(d[1]), "+f"(d[2]), "+f"(d[3])
        : "r"(a[0]), "r"(a[1]), "r"(a[2]), "r"(a[3]), "r"(b0), "r"(b1));
}

// ---------------------------------------------------------------------------
// Kernel 1: LayerNorm -> fp16
// ---------------------------------------------------------------------------
__global__ __launch_bounds__(256) void ln_h_kernel(
    const float* __restrict__ x,
    const float* __restrict__ gamma,
    const float* __restrict__ beta)
{
    const int row = blockIdx.x;
    const int tid = threadIdx.x;
    const float* xr = x + (size_t)row * K_DIM;

    float v0 = xr[tid];
    float v1 = xr[tid + 256];
    float v2 = xr[tid + 512];

    float s  = v0 + v1 + v2;
    float s2 = v0 * v0 + v1 * v1 + v2 * v2;

    __shared__ float red[2][32];
    #pragma unroll
    for (int off = 16; off > 0; off >>= 1) {
        s  += __shfl_xor_sync(0xffffffffu, s,  off);
        s2 += __shfl_xor_sync(0xffffffffu, s2, off);
    }
    const int wid = tid >> 5, lid = tid & 31;
    if (lid == 0) { red[0][wid] = s; red[1][wid] = s2; }
    __syncthreads();
    if (wid == 0) {
        s  = (lid < 8) ? red[0][lid] : 0.0f;
        s2 = (lid < 8) ? red[1][lid] : 0.0f;
        #pragma unroll
        for (int off = 4; off > 0; off >>= 1) {
            s  += __shfl_xor_sync(0xffffffffu, s,  off);
            s2 += __shfl_xor_sync(0xffffffffu, s2, off);
        }
        if (lid == 0) { red[0][0] = s; red[1][0] = s2; }
    }
    __syncthreads();
    const float inv_n = 1.0f / (float)K_DIM;
    const float mu  = red[0][0] * inv_n;
    const float var = fmaxf(red[1][0] * inv_n - mu * mu, 0.0f);
    const float rstd = rsqrtf(var + 1e-12f);

    #pragma unroll
    for (int i = 0; i < 3; i++) {
        const int c = tid + i * 256;
        float v = (i == 0) ? v0 : (i == 1 ? v1 : v2);
        float xn = (v - mu) * rstd * gamma[c] + beta[c];
        g_A[(size_t)row * K_DIM + c] = f2h(xn);
    }
}

// ---------------------------------------------------------------------------
// Kernel 2: transpose W [K,N] -> [N,K] fp16
// ---------------------------------------------------------------------------
__global__ __launch_bounds__(256) void wt_h_kernel(const float* __restrict__ W)
{
    __shared__ float tile[32][33];
    const int tx = threadIdx.x, ty = threadIdx.y;   // block (32, 8)
    const int n0 = blockIdx.x * 32, k0 = blockIdx.y * 32;

    #pragma unroll
    for (int j = 0; j < 4; j++)
        tile[ty + 8 * j][tx] = W[(size_t)(k0 + ty + 8 * j) * N_DIM + n0 + tx];
    __syncthreads();
    #pragma unroll
    for (int j = 0; j < 4; j++)
        g_B[(size_t)(n0 + ty + 8 * j) * K_DIM + k0 + tx] = f2h(tile[tx][ty + 8 * j]);
}

// ---------------------------------------------------------------------------
// Kernel 3: fp16 single-pass mma.sync GEMM + bias + exact erf GELU
// CTA tile 128x128, BK=32, 2-stage cp.async, 8 warps (warp tile 32x64).
// ---------------------------------------------------------------------------
#define BM 128
#define BN 128
#define BK 32
#define ROWH 40          // halves per smem row (32 data + 8 pad)
#define NSTEP 24         // 768 / 32

__global__ __launch_bounds__(256, 2) void gemm_f16_kernel(
    const float* __restrict__ bias, float* __restrict__ C)
{
    __shared__ uint16_t As[2][BM * ROWH];
    __shared__ uint16_t Bs[2][BN * ROWH];

    const int tid = threadIdx.x;
    const int wid = tid >> 5, lane = tid & 31;
    const int bn = blockIdx.x * BN;
    const int bm = blockIdx.y * BM;
    const int wm = (wid >> 1) * 32;   // 4 warps along M
    const int wn = (wid & 1) * 64;    // 2 warps along N

    float acc[2][8][4];
    #pragma unroll
    for (int mt = 0; mt < 2; mt++)
        #pragma unroll
        for (int nt = 0; nt < 8; nt++)
            #pragma unroll
            for (int q = 0; q < 4; q++) acc[mt][nt][q] = 0.0f;

    const uint32_t sA0 = smem_u32(&As[0][0]);
    const uint32_t sB0 = smem_u32(&Bs[0][0]);
    const uint32_t stageA = (uint32_t)(BM * ROWH * 2);
    const uint32_t stageB = (uint32_t)(BN * ROWH * 2);

    auto load_stage = [&](int st, int step) {
        const int k0 = step * BK;
        #pragma unroll
        for (int i = 0; i < 2; i++) {
            const int idx = tid + i * 256;       // 0..511
            const int r = idx >> 2, c = idx & 3; // row, 16B chunk
            const uint32_t soff = (uint32_t)(r * ROWH + c * 8) * 2;
            cp_async16(sA0 + st * stageA + soff,
                       g_A + (size_t)(bm + r) * K_DIM + k0 + c * 8);
            cp_async16(sB0 + st * stageB + soff,
                       g_B + (size_t)(bn + r) * K_DIM + k0 + c * 8);
        }
        CP_COMMIT();
    };

    load_stage(0, 0);

    for (int step = 0; step < NSTEP; step++) {
        const int st = step & 1;
        if (step + 1 < NSTEP) {
            load_stage(st ^ 1, step + 1);
            CP_WAIT(1);
        } else {
            CP_WAIT(0);
        }
        __syncthreads();

        #pragma unroll
        for (int kk = 0; kk < 2; kk++) {        // two k16 steps per BK=32
            const int chunk = kk * 2 + (lane >> 4);
            uint32_t a[2][4];
            #pragma unroll
            for (int mt = 0; mt < 2; mt++) {
                const int row = wm + mt * 16 + (lane & 15);
                ldmatrix_x4(a[mt], sA0 + st * stageA
                                   + (uint32_t)(row * ROWH) * 2 + chunk * 16);
            }
            uint32_t b[4][4];
            #pragma unroll
            for (int g = 0; g < 4; g++) {
                const int row = wn + g * 16 + (lane & 15);
                ldmatrix_x4(b[g], sB0 + st * stageB
                                  + (uint32_t)(row * ROWH) * 2 + chunk * 16);
            }
            #pragma unroll
            for (int mt = 0; mt < 2; mt++)
                #pragma unroll
                for (int nt = 0; nt < 8; nt++)
                    mma_f16(acc[mt][nt], a[mt],
                            b[nt >> 1][nt & 1], b[nt >> 1][2 + (nt & 1)]);
        }
        __syncthreads();
    }

    // epilogue: bias + exact erf GELU
    const int r0 = bm + wm + (lane >> 2);
    const int c0 = bn + wn + (lane & 3) * 2;
    #pragma unroll
    for (int mt = 0; mt < 2; mt++) {
        #pragma unroll
        for (int nt = 0; nt < 8; nt++) {
            const int col = c0 + nt * 8;
            const float b0 = bias[col], b1 = bias[col + 1];
            #pragma unroll
            for (int half = 0; half < 2; half++) {
                const int row = r0 + mt * 16 + half * 8;
                float h0 = acc[mt][nt][half * 2 + 0] + b0;
                float h1 = acc[mt][nt][half * 2 + 1] + b1;
                float2 o;
                o.x = 0.5f * h0 * (1.0f + erff(h0 * 0.70710678118654752f));
                o.y = 0.5f * h1 * (1.0f + erff(h1 * 0.70710678118654752f));
                *(float2*)&C[(size_t)row * N_DIM + col] = o;
            }
        }
    }
}

// ---------------------------------------------------------------------------
extern "C" void kernel_launch(void* const* d_in, const int* in_sizes, int n_in,
                              void* d_out, int out_size)
{
    const float* x     = (const float*)d_in[0];
    const float* gamma = (const float*)d_in[1];
    const float* beta  = (const float*)d_in[2];
    const float* W     = (const float*)d_in[3];
    const float* b     = (const float*)d_in[4];
    float* out = (float*)d_out;

    ln_h_kernel<<<M_DIM, 256>>>(x, gamma, beta);
    wt_h_kernel<<<dim3(N_DIM / 32, K_DIM / 32), dim3(32, 8)>>>(W);
    gemm_f16_kernel<<<dim3(N_DIM / BN, M_DIM / BM), 256>>>(b, out);
}

// round 6
// speedup vs baseline: 5.5885x; 1.0261x over previous
#include <cuda_runtime.h>
#include <cstdint>
#include <math.h>

#define M_DIM 16384
#define K_DIM 768
#define N_DIM 3072

// ---------------- scratch (no cudaMalloc allowed) ----------------
__device__ uint16_t g_A[M_DIM * K_DIM];    // fp16 bits, LN output
__device__ uint16_t g_B[N_DIM * K_DIM];    // fp16 bits, W transposed [N, K]

// ---------------- helpers ----------------
__device__ __forceinline__ uint32_t smem_u32(const void* p) {
    uint32_t a;
    asm("{ .reg .u64 t; cvta.to.shared.u64 t, %1; cvt.u32.u64 %0, t; }" : "=r"(a) : "l"(p));
    return a;
}
__device__ __forceinline__ uint16_t f2h(float x) {
    uint16_t h;
    asm("cvt.rn.f16.f32 %0, %1;" : "=h"(h) : "f"(x));
    return h;
}
__device__ __forceinline__ uint32_t pack_h2(float a, float b) {
    return (uint32_t)f2h(a) | ((uint32_t)f2h(b) << 16);
}
__device__ __forceinline__ void cp_async16(uint32_t dst, const void* src) {
    asm volatile("cp.async.cg.shared.global [%0], [%1], 16;"
                 :: "r"(dst), "l"(__cvta_generic_to_global(src)) : "memory");
}
#define CP_COMMIT() asm volatile("cp.async.commit_group;" ::: "memory")
#define CP_WAIT(n)  asm volatile("cp.async.wait_group %0;" :: "n"(n) : "memory")

__device__ __forceinline__ void ldmatrix_x4(uint32_t* r, uint32_t addr) {
    asm volatile("ldmatrix.sync.aligned.m8n8.x4.shared.b16 {%0,%1,%2,%3}, [%4];"
                 : "=r"(r[0]), "=r"(r[1]), "=r"(r[2]), "=r"(r[3]) : "r"(addr));
}
__device__ __forceinline__ void mma_f16(float* d, const uint32_t* a,
                                        uint32_t b0, uint32_t b1) {
    asm volatile(
        "mma.sync.aligned.m16n8k16.row.col.f32.f16.f16.f32 "
        "{%0,%1,%2,%3}, {%4,%5,%6,%7}, {%8,%9}, {%0,%1,%2,%3};"
        : "+f"(d[0]), "+f"(d[1]), "+f"(d[2]), "+f"(d[3])
        : "r"(a[0]), "r"(a[1]), "r"(a[2]), "r"(a[3]), "r"(b0), "r"(b1));
}

// ---------------------------------------------------------------------------
// Kernel 1: LayerNorm -> fp16, 4 rows/block, 64 threads/row, float4 I/O
// ---------------------------------------------------------------------------
__global__ __launch_bounds__(256) void ln_h_kernel(
    const float* __restrict__ x,
    const float* __restrict__ gamma,
    const float* __restrict__ beta)
{
    const int tid = threadIdx.x;
    const int rloc = tid >> 6;                  // 0..3
    const int t = tid & 63;                     // 0..63
    const int row = blockIdx.x * 4 + rloc;
    const float4* xr = (const float4*)(x + (size_t)row * K_DIM);

    float4 v[3];
    #pragma unroll
    for (int j = 0; j < 3; j++) v[j] = xr[t + 64 * j];

    float s = 0.0f, s2 = 0.0f;
    #pragma unroll
    for (int j = 0; j < 3; j++) {
        s  += v[j].x + v[j].y + v[j].z + v[j].w;
        s2 += v[j].x * v[j].x + v[j].y * v[j].y + v[j].z * v[j].z + v[j].w * v[j].w;
    }

    #pragma unroll
    for (int off = 16; off > 0; off >>= 1) {
        s  += __shfl_xor_sync(0xffffffffu, s,  off);
        s2 += __shfl_xor_sync(0xffffffffu, s2, off);
    }
    __shared__ float red[4][2][2];
    const int wir = (t >> 5);                   // warp within row: 0/1
    if ((t & 31) == 0) { red[rloc][wir][0] = s; red[rloc][wir][1] = s2; }
    __syncthreads();
    s  = red[rloc][0][0] + red[rloc][1][0];
    s2 = red[rloc][0][1] + red[rloc][1][1];

    const float inv_n = 1.0f / (float)K_DIM;
    const float mu  = s * inv_n;
    const float var = fmaxf(s2 * inv_n - mu * mu, 0.0f);
    const float rstd = rsqrtf(var + 1e-12f);

    uint2* outr = (uint2*)(g_A + (size_t)row * K_DIM);
    #pragma unroll
    for (int j = 0; j < 3; j++) {
        const float4 g = ((const float4*)gamma)[t + 64 * j];
        const float4 be = ((const float4*)beta)[t + 64 * j];
        float x0 = (v[j].x - mu) * rstd * g.x + be.x;
        float x1 = (v[j].y - mu) * rstd * g.y + be.y;
        float x2 = (v[j].z - mu) * rstd * g.z + be.z;
        float x3 = (v[j].w - mu) * rstd * g.w + be.w;
        uint2 o;
        o.x = pack_h2(x0, x1);
        o.y = pack_h2(x2, x3);
        outr[t + 64 * j] = o;
    }
}

// ---------------------------------------------------------------------------
// Kernel 2: transpose W [K,N] -> [N,K] fp16
// ---------------------------------------------------------------------------
__global__ __launch_bounds__(256) void wt_h_kernel(const float* __restrict__ W)
{
    __shared__ float tile[32][33];
    const int tx = threadIdx.x, ty = threadIdx.y;   // block (32, 8)
    const int n0 = blockIdx.x * 32, k0 = blockIdx.y * 32;

    #pragma unroll
    for (int j = 0; j < 4; j++)
        tile[ty + 8 * j][tx] = W[(size_t)(k0 + ty + 8 * j) * N_DIM + n0 + tx];
    __syncthreads();
    #pragma unroll
    for (int j = 0; j < 4; j++)
        g_B[(size_t)(n0 + ty + 8 * j) * K_DIM + k0 + tx] = f2h(tile[tx][ty + 8 * j]);
}

// ---------------------------------------------------------------------------
// Kernel 3: fp16 single-pass mma.sync GEMM + bias + exact erf GELU
// CTA 128x128, BK=32, 3-stage cp.async, ONE __syncthreads per step.
// ---------------------------------------------------------------------------
#define BM 128
#define BN 128
#define BK 32
#define ROWH 40          // halves per smem row (32 data + 8 pad)
#define NSTEP 24         // 768 / 32
#define NSTAGE 3

__global__ __launch_bounds__(256, 2) void gemm_f16_kernel(
    const float* __restrict__ bias, float* __restrict__ C)
{
    __shared__ uint16_t As[NSTAGE][BM * ROWH];
    __shared__ uint16_t Bs[NSTAGE][BN * ROWH];

    const int tid = threadIdx.x;
    const int wid = tid >> 5, lane = tid & 31;
    const int bn = blockIdx.x * BN;
    const int bm = blockIdx.y * BM;
    const int wm = (wid >> 1) * 32;   // 4 warps along M
    const int wn = (wid & 1) * 64;    // 2 warps along N

    float acc[2][8][4];
    #pragma unroll
    for (int mt = 0; mt < 2; mt++)
        #pragma unroll
        for (int nt = 0; nt < 8; nt++)
            #pragma unroll
            for (int q = 0; q < 4; q++) acc[mt][nt][q] = 0.0f;

    const uint32_t sA0 = smem_u32(&As[0][0]);
    const uint32_t sB0 = smem_u32(&Bs[0][0]);
    const uint32_t stageA = (uint32_t)(BM * ROWH * 2);
    const uint32_t stageB = (uint32_t)(BN * ROWH * 2);

    // per-thread cp.async geometry (2 chunks per operand per thread)
    const int r_ld  = tid >> 2;            // rows 0..63 (idx 0) / 64..127 (idx 1)
    const int c_ld  = (tid & 3) * 8;       // half offset of 16B chunk

    auto load_stage = [&](int st, int step) {
        const int k0 = step * BK;
        #pragma unroll
        for (int i = 0; i < 2; i++) {
            const int r = r_ld + i * 64;
            const uint32_t soff = (uint32_t)(r * ROWH + c_ld) * 2;
            cp_async16(sA0 + st * stageA + soff,
                       g_A + (size_t)(bm + r) * K_DIM + k0 + c_ld);
            cp_async16(sB0 + st * stageB + soff,
                       g_B + (size_t)(bn + r) * K_DIM + k0 + c_ld);
        }
        CP_COMMIT();
    };

    load_stage(0, 0);
    load_stage(1, 1);

    for (int step = 0; step < NSTEP; step++) {
        const int st = step % NSTAGE;
        if (step < NSTEP - 1) { CP_WAIT(1); } else { CP_WAIT(0); }
        __syncthreads();

        #pragma unroll
        for (int kk = 0; kk < 2; kk++) {        // two k16 steps per BK=32
            const int chunk = kk * 2 + (lane >> 4);
            uint32_t a[2][4];
            #pragma unroll
            for (int mt = 0; mt < 2; mt++) {
                const int row = wm + mt * 16 + (lane & 15);
                ldmatrix_x4(a[mt], sA0 + st * stageA
                                   + (uint32_t)(row * ROWH) * 2 + chunk * 16);
            }
            uint32_t b[4][4];
            #pragma unroll
            for (int g = 0; g < 4; g++) {
                const int row = wn + g * 16 + (lane & 15);
                ldmatrix_x4(b[g], sB0 + st * stageB
                                  + (uint32_t)(row * ROWH) * 2 + chunk * 16);
            }
            #pragma unroll
            for (int mt = 0; mt < 2; mt++)
                #pragma unroll
                for (int nt = 0; nt < 8; nt++)
                    mma_f16(acc[mt][nt], a[mt],
                            b[nt >> 1][nt & 1], b[nt >> 1][2 + (nt & 1)]);
        }

        // issue next prefetch AFTER compute: slot (step+2)%3 was consumed at
        // step-1, and every warp passed this step's barrier only after
        // finishing step-1's compute -> safe with a single barrier per step.
        if (step + 2 < NSTEP) load_stage((step + 2) % NSTAGE, step + 2);
    }

    // epilogue: bias + exact erf GELU
    const int r0 = bm + wm + (lane >> 2);
    const int c0 = bn + wn + (lane & 3) * 2;
    #pragma unroll
    for (int mt = 0; mt < 2; mt++) {
        #pragma unroll
        for (int nt = 0; nt < 8; nt++) {
            const int col = c0 + nt * 8;
            const float b0 = __ldg(&bias[col]), b1 = __ldg(&bias[col + 1]);
            #pragma unroll
            for (int half = 0; half < 2; half++) {
                const int row = r0 + mt * 16 + half * 8;
                float h0 = acc[mt][nt][half * 2 + 0] + b0;
                float h1 = acc[mt][nt][half * 2 + 1] + b1;
                float2 o;
                o.x = 0.5f * h0 * (1.0f + erff(h0 * 0.70710678118654752f));
                o.y = 0.5f * h1 * (1.0f + erff(h1 * 0.70710678118654752f));
                *(float2*)&C[(size_t)row * N_DIM + col] = o;
            }
        }
    }
}

// ---------------------------------------------------------------------------
extern "C" void kernel_launch(void* const* d_in, const int* in_sizes, int n_in,
                              void* d_out, int out_size)
{
    const float* x     = (const float*)d_in[0];
    const float* gamma = (const float*)d_in[1];
    const float* beta  = (const float*)d_in[2];
    const float* W     = (const float*)d_in[3];
    const float* b     = (const float*)d_in[4];
    float* out = (float*)d_out;

    ln_h_kernel<<<M_DIM / 4, 256>>>(x, gamma, beta);
    wt_h_kernel<<<dim3(N_DIM / 32, K_DIM / 32), dim3(32, 8)>>>(W);
    gemm_f16_kernel<<<dim3(N_DIM / BN, M_DIM / BM), 256>>>(b, out);
}

// round 7
// speedup vs baseline: 5.5906x; 1.0004x over previous
#include <cuda_runtime.h>
#include <cstdint>
#include <math.h>

#define M_DIM 16384
#define K_DIM 768
#define N_DIM 3072

// ---------------- scratch (no cudaMalloc allowed) ----------------
__device__ uint16_t g_A[M_DIM * K_DIM];    // fp16 bits, LN output
__device__ uint16_t g_B[N_DIM * K_DIM];    // fp16 bits, W transposed [N, K]

// ---------------- helpers ----------------
__device__ __forceinline__ uint32_t smem_u32(const void* p) {
    uint32_t a;
    asm("{ .reg .u64 t; cvta.to.shared.u64 t, %1; cvt.u32.u64 %0, t; }" : "=r"(a) : "l"(p));
    return a;
}
__device__ __forceinline__ uint16_t f2h(float x) {
    uint16_t h;
    asm("cvt.rn.f16.f32 %0, %1;" : "=h"(h) : "f"(x));
    return h;
}
// pack (lo, hi) into one f16x2 register with a single cvt (first src = high half)
__device__ __forceinline__ uint32_t pack_h2(float lo, float hi) {
    uint32_t r;
    asm("cvt.rn.f16x2.f32 %0, %1, %2;" : "=r"(r) : "f"(hi), "f"(lo));
    return r;
}
__device__ __forceinline__ void cp_async16(uint32_t dst, const void* src) {
    asm volatile("cp.async.cg.shared.global [%0], [%1], 16;"
                 :: "r"(dst), "l"(__cvta_generic_to_global(src)) : "memory");
}
#define CP_COMMIT() asm volatile("cp.async.commit_group;" ::: "memory")
#define CP_WAIT(n)  asm volatile("cp.async.wait_group %0;" :: "n"(n) : "memory")

__device__ __forceinline__ void ldmatrix_x4(uint32_t* r, uint32_t addr) {
    asm volatile("ldmatrix.sync.aligned.m8n8.x4.shared.b16 {%0,%1,%2,%3}, [%4];"
                 : "=r"(r[0]), "=r"(r[1]), "=r"(r[2]), "=r"(r[3]) : "r"(addr));
}
__device__ __forceinline__ void mma_f16(float* d, const uint32_t* a,
                                        uint32_t b0, uint32_t b1) {
    asm volatile(
        "mma.sync.aligned.m16n8k16.row.col.f32.f16.f16.f32 "
        "{%0,%1,%2,%3}, {%4,%5,%6,%7}, {%8,%9}, {%0,%1,%2,%3};"
        : "+f"(d[0]), "+f"(d[1]), "+f"(d[2]), "+f"(d[3])
        : "r"(a[0]), "r"(a[1]), "r"(a[2]), "r"(a[3]), "r"(b0), "r"(b1));
}

// ---------------------------------------------------------------------------
// Kernel 1: LayerNorm -> fp16, 4 rows/block, 64 threads/row, float4 I/O,
// f16x2 packed converts.
// ---------------------------------------------------------------------------
__global__ __launch_bounds__(256) void ln_h_kernel(
    const float* __restrict__ x,
    const float* __restrict__ gamma,
    const float* __restrict__ beta)
{
    const int tid = threadIdx.x;
    const int rloc = tid >> 6;                  // 0..3
    const int t = tid & 63;                     // 0..63
    const int row = blockIdx.x * 4 + rloc;
    const float4* xr = (const float4*)(x + (size_t)row * K_DIM);

    float4 v[3];
    #pragma unroll
    for (int j = 0; j < 3; j++) v[j] = xr[t + 64 * j];

    float s = 0.0f, s2 = 0.0f;
    #pragma unroll
    for (int j = 0; j < 3; j++) {
        s  += v[j].x + v[j].y + v[j].z + v[j].w;
        s2 += v[j].x * v[j].x + v[j].y * v[j].y + v[j].z * v[j].z + v[j].w * v[j].w;
    }

    #pragma unroll
    for (int off = 16; off > 0; off >>= 1) {
        s  += __shfl_xor_sync(0xffffffffu, s,  off);
        s2 += __shfl_xor_sync(0xffffffffu, s2, off);
    }
    __shared__ float red[4][2][2];
    const int wir = (t >> 5);                   // warp within row: 0/1
    if ((t & 31) == 0) { red[rloc][wir][0] = s; red[rloc][wir][1] = s2; }
    __syncthreads();
    s  = red[rloc][0][0] + red[rloc][1][0];
    s2 = red[rloc][0][1] + red[rloc][1][1];

    const float inv_n = 1.0f / (float)K_DIM;
    const float mu  = s * inv_n;
    const float var = fmaxf(s2 * inv_n - mu * mu, 0.0f);
    const float rstd = rsqrtf(var + 1e-12f);

    uint2* outr = (uint2*)(g_A + (size_t)row * K_DIM);
    #pragma unroll
    for (int j = 0; j < 3; j++) {
        const float4 g = ((const float4*)gamma)[t + 64 * j];
        const float4 be = ((const float4*)beta)[t + 64 * j];
        float x0 = (v[j].x - mu) * rstd * g.x + be.x;
        float x1 = (v[j].y - mu) * rstd * g.y + be.y;
        float x2 = (v[j].z - mu) * rstd * g.z + be.z;
        float x3 = (v[j].w - mu) * rstd * g.w + be.w;
        uint2 o;
        o.x = pack_h2(x0, x1);
        o.y = pack_h2(x2, x3);
        outr[t + 64 * j] = o;
    }
}

// ---------------------------------------------------------------------------
// Kernel 2: transpose W [K,N] -> [N,K] fp16.
// 64(K) x 32(N) tile; coalesced fp32 loads; 16B uint4 stores along K.
// ---------------------------------------------------------------------------
__global__ __launch_bounds__(256) void wt_h_kernel(const float* __restrict__ W)
{
    __shared__ float tile[64][33];
    const int tx = threadIdx.x, ty = threadIdx.y;   // block (32, 8)
    const int n0 = blockIdx.x * 32, k0 = blockIdx.y * 64;

    #pragma unroll
    for (int j = 0; j < 8; j++)
        tile[ty + 8 * j][tx] = W[(size_t)(k0 + ty + 8 * j) * N_DIM + n0 + tx];
    __syncthreads();

    // thread (tx = local n, ty = 8-wide k chunk) writes 8 halves = 16B
    uint4 o;
    o.x = pack_h2(tile[ty * 8 + 0][tx], tile[ty * 8 + 1][tx]);
    o.y = pack_h2(tile[ty * 8 + 2][tx], tile[ty * 8 + 3][tx]);
    o.z = pack_h2(tile[ty * 8 + 4][tx], tile[ty * 8 + 5][tx]);
    o.w = pack_h2(tile[ty * 8 + 6][tx], tile[ty * 8 + 7][tx]);
    *(uint4*)&g_B[(size_t)(n0 + tx) * K_DIM + k0 + ty * 8] = o;
}

// ---------------------------------------------------------------------------
// Kernel 3: fp16 single-pass mma.sync GEMM + bias + exact erf GELU
// CTA 128x128, BK=32, 3-stage cp.async, ONE __syncthreads per step.
// (unchanged from R6 — at the legacy-HMMA issue floor)
// ---------------------------------------------------------------------------
#define BM 128
#define BN 128
#define BK 32
#define ROWH 40          // halves per smem row (32 data + 8 pad)
#define NSTEP 24         // 768 / 32
#define NSTAGE 3

__global__ __launch_bounds__(256, 2) void gemm_f16_kernel(
    const float* __restrict__ bias, float* __restrict__ C)
{
    __shared__ uint16_t As[NSTAGE][BM * ROWH];
    __shared__ uint16_t Bs[NSTAGE][BN * ROWH];

    const int tid = threadIdx.x;
    const int wid = tid >> 5, lane = tid & 31;
    const int bn = blockIdx.x * BN;
    const int bm = blockIdx.y * BM;
    const int wm = (wid >> 1) * 32;   // 4 warps along M
    const int wn = (wid & 1) * 64;    // 2 warps along N

    float acc[2][8][4];
    #pragma unroll
    for (int mt = 0; mt < 2; mt++)
        #pragma unroll
        for (int nt = 0; nt < 8; nt++)
            #pragma unroll
            for (int q = 0; q < 4; q++) acc[mt][nt][q] = 0.0f;

    const uint32_t sA0 = smem_u32(&As[0][0]);
    const uint32_t sB0 = smem_u32(&Bs[0][0]);
    const uint32_t stageA = (uint32_t)(BM * ROWH * 2);
    const uint32_t stageB = (uint32_t)(BN * ROWH * 2);

    const int r_ld  = tid >> 2;            // rows 0..63 / +64
    const int c_ld  = (tid & 3) * 8;       // half offset of 16B chunk

    auto load_stage = [&](int st, int step) {
        const int k0 = step * BK;
        #pragma unroll
        for (int i = 0; i < 2; i++) {
            const int r = r_ld + i * 64;
            const uint32_t soff = (uint32_t)(r * ROWH + c_ld) * 2;
            cp_async16(sA0 + st * stageA + soff,
                       g_A + (size_t)(bm + r) * K_DIM + k0 + c_ld);
            cp_async16(sB0 + st * stageB + soff,
                       g_B + (size_t)(bn + r) * K_DIM + k0 + c_ld);
        }
        CP_COMMIT();
    };

    load_stage(0, 0);
    load_stage(1, 1);

    for (int step = 0; step < NSTEP; step++) {
        const int st = step % NSTAGE;
        if (step < NSTEP - 1) { CP_WAIT(1); } else { CP_WAIT(0); }
        __syncthreads();

        #pragma unroll
        for (int kk = 0; kk < 2; kk++) {        // two k16 steps per BK=32
            const int chunk = kk * 2 + (lane >> 4);
            uint32_t a[2][4];
            #pragma unroll
            for (int mt = 0; mt < 2; mt++) {
                const int row = wm + mt * 16 + (lane & 15);
                ldmatrix_x4(a[mt], sA0 + st * stageA
                                   + (uint32_t)(row * ROWH) * 2 + chunk * 16);
            }
            uint32_t b[4][4];
            #pragma unroll
            for (int g = 0; g < 4; g++) {
                const int row = wn + g * 16 + (lane & 15);
                ldmatrix_x4(b[g], sB0 + st * stageB
                                  + (uint32_t)(row * ROWH) * 2 + chunk * 16);
            }
            #pragma unroll
            for (int mt = 0; mt < 2; mt++)
                #pragma unroll
                for (int nt = 0; nt < 8; nt++)
                    mma_f16(acc[mt][nt], a[mt],
                            b[nt >> 1][nt & 1], b[nt >> 1][2 + (nt & 1)]);
        }

        if (step + 2 < NSTEP) load_stage((step + 2) % NSTAGE, step + 2);
    }

    // epilogue: bias + exact erf GELU
    const int r0 = bm + wm + (lane >> 2);
    const int c0 = bn + wn + (lane & 3) * 2;
    #pragma unroll
    for (int mt = 0; mt < 2; mt++) {
        #pragma unroll
        for (int nt = 0; nt < 8; nt++) {
            const int col = c0 + nt * 8;
            const float b0 = __ldg(&bias[col]), b1 = __ldg(&bias[col + 1]);
            #pragma unroll
            for (int half = 0; half < 2; half++) {
                const int row = r0 + mt * 16 + half * 8;
                float h0 = acc[mt][nt][half * 2 + 0] + b0;
                float h1 = acc[mt][nt][half * 2 + 1] + b1;
                float2 o;
                o.x = 0.5f * h0 * (1.0f + erff(h0 * 0.70710678118654752f));
                o.y = 0.5f * h1 * (1.0f + erff(h1 * 0.70710678118654752f));
                *(float2*)&C[(size_t)row * N_DIM + col] = o;
            }
        }
    }
}

// ---------------------------------------------------------------------------
extern "C" void kernel_launch(void* const* d_in, const int* in_sizes, int n_in,
                              void* d_out, int out_size)
{
    const float* x     = (const float*)d_in[0];
    const float* gamma = (const float*)d_in[1];
    const float* beta  = (const float*)d_in[2];
    const float* W     = (const float*)d_in[3];
    const float* b     = (const float*)d_in[4];
    float* out = (float*)d_out;

    ln_h_kernel<<<M_DIM / 4, 256>>>(x, gamma, beta);
    wt_h_kernel<<<dim3(N_DIM / 32, K_DIM / 64), dim3(32, 8)>>>(W);
    gemm_f16_kernel<<<dim3(N_DIM / BN, M_DIM / BM), 256>>>(b, out);
}